// round 1
// baseline (speedup 1.0000x reference)
#include <cuda_runtime.h>

#define NUM_CLASSES 1000
#define FEAT_DIM    256
#define NROWS       262144

// Device-global scratch (no allocation allowed in kernel_launch).
__device__ int g_count[NUM_CLASSES];
__device__ int g_offset[NUM_CLASSES];
__device__ int g_cursor[NUM_CLASSES];
__device__ int g_idx[NROWS];

// ---------------------------------------------------------------------------
// Kernel 0: zero the class-count array (graph-replayed, must re-init per call)
// ---------------------------------------------------------------------------
__global__ void k_init() {
    int i = blockIdx.x * blockDim.x + threadIdx.x;
    if (i < NUM_CLASSES) g_count[i] = 0;
}

// ---------------------------------------------------------------------------
// Kernel 1: label histogram, shared-memory privatized
// ---------------------------------------------------------------------------
__global__ void k_hist(const int* __restrict__ labels, int n) {
    __shared__ int h[NUM_CLASSES];
    for (int i = threadIdx.x; i < NUM_CLASSES; i += blockDim.x) h[i] = 0;
    __syncthreads();
    for (int i = blockIdx.x * blockDim.x + threadIdx.x; i < n;
         i += gridDim.x * blockDim.x) {
        atomicAdd(&h[labels[i]], 1);
    }
    __syncthreads();
    for (int i = threadIdx.x; i < NUM_CLASSES; i += blockDim.x) {
        int v = h[i];
        if (v) atomicAdd(&g_count[i], v);
    }
}

// ---------------------------------------------------------------------------
// Kernel 2: exclusive scan over 1000 counts (single block, Hillis-Steele)
// ---------------------------------------------------------------------------
__global__ void k_scan() {
    __shared__ int s[1024];
    int t = threadIdx.x;
    s[t] = (t < NUM_CLASSES) ? g_count[t] : 0;
    for (int off = 1; off < 1024; off <<= 1) {
        __syncthreads();
        int v = (t >= off) ? s[t - off] : 0;
        __syncthreads();
        s[t] += v;
    }
    __syncthreads();
    int excl = (t == 0) ? 0 : s[t - 1];
    if (t < NUM_CLASSES) {
        g_offset[t] = excl;
        g_cursor[t] = excl;
    }
}

// ---------------------------------------------------------------------------
// Kernel 3: scatter row indices into class-sorted order
// ---------------------------------------------------------------------------
__global__ void k_scatter(const int* __restrict__ labels, int n) {
    for (int i = blockIdx.x * blockDim.x + threadIdx.x; i < n;
         i += gridDim.x * blockDim.x) {
        int c = labels[i];
        int pos = atomicAdd(&g_cursor[c], 1);
        g_idx[pos] = i;
    }
}

// ---------------------------------------------------------------------------
// Kernel 4: per-class coalesced segment sum + EMA epilogue.
// One block per class, one thread per feature dim. All feature reads are
// 128B-line coalesced; zero atomics. 4 accumulators for MLP.
// ---------------------------------------------------------------------------
__global__ void __launch_bounds__(256, 8)
k_reduce(const float* __restrict__ feats,
         const float* __restrict__ protos,
         float* __restrict__ out) {
    int c = blockIdx.x;
    int t = threadIdx.x;
    int start = g_offset[c];
    int cnt   = g_count[c];

    __shared__ int sidx[256];
    float s0 = 0.f, s1 = 0.f, s2 = 0.f, s3 = 0.f;

    for (int base = 0; base < cnt; base += 256) {
        int m = min(256, cnt - base);
        if (t < m) sidx[t] = g_idx[start + base + t];
        __syncthreads();
        int j = 0;
        for (; j + 4 <= m; j += 4) {
            long r0 = sidx[j + 0];
            long r1 = sidx[j + 1];
            long r2 = sidx[j + 2];
            long r3 = sidx[j + 3];
            s0 += feats[r0 * FEAT_DIM + t];
            s1 += feats[r1 * FEAT_DIM + t];
            s2 += feats[r2 * FEAT_DIM + t];
            s3 += feats[r3 * FEAT_DIM + t];
        }
        for (; j < m; j++) {
            s0 += feats[(long)sidx[j] * FEAT_DIM + t];
        }
        __syncthreads();
    }

    float sum = (s0 + s1) + (s2 + s3);
    float p = protos[c * FEAT_DIM + t];
    float r = p;
    if (cnt > 0) {
        float mean = sum / (float)cnt;
        r = 0.9f * p + 0.1f * mean;
    }
    out[c * FEAT_DIM + t] = r;
}

// ---------------------------------------------------------------------------
// Launch
// ---------------------------------------------------------------------------
extern "C" void kernel_launch(void* const* d_in, const int* in_sizes, int n_in,
                              void* d_out, int out_size) {
    const float* features   = (const float*)d_in[0];
    const int*   labels     = (const int*)d_in[1];   // labels in [0,1000)
    const float* prototypes = (const float*)d_in[2];
    float*       out        = (float*)d_out;

    int n = in_sizes[1];  // number of rows / labels

    k_init<<<(NUM_CLASSES + 255) / 256, 256>>>();
    k_hist<<<256, 256>>>(labels, n);
    k_scan<<<1, 1024>>>();
    k_scatter<<<512, 256>>>(labels, n);
    k_reduce<<<NUM_CLASSES, 256>>>(features, prototypes, out);
}

// round 2
// speedup vs baseline: 1.2126x; 1.2126x over previous
#include <cuda_runtime.h>

#define NUM_CLASSES 1000
#define FEAT_DIM    256
#define NROWS       262144
#define NBLK        256          // chunks for hierarchical counting sort

// Device-global scratch (no allocation allowed in kernel_launch).
__device__ int g_hist[NBLK * NUM_CLASSES];   // per-block hist -> per-block excl prefix
__device__ int g_count[NUM_CLASSES];
__device__ int g_offset[NUM_CLASSES];
__device__ int g_idx[NROWS];

// ---------------------------------------------------------------------------
// Kernel 1: per-block label histogram (smem privatized, no global atomics)
// Block b owns rows [b*rpb, (b+1)*rpb).
// ---------------------------------------------------------------------------
__global__ void k_hist(const int* __restrict__ labels, int n, int rpb) {
    __shared__ int h[NUM_CLASSES];
    for (int i = threadIdx.x; i < NUM_CLASSES; i += blockDim.x) h[i] = 0;
    __syncthreads();
    int base = blockIdx.x * rpb;
    for (int j = threadIdx.x; j < rpb; j += blockDim.x) {
        int r = base + j;
        if (r < n) atomicAdd(&h[labels[r]], 1);
    }
    __syncthreads();
    int* dst = &g_hist[blockIdx.x * NUM_CLASSES];
    for (int i = threadIdx.x; i < NUM_CLASSES; i += blockDim.x) dst[i] = h[i];
}

// ---------------------------------------------------------------------------
// Kernel 2: per-class exclusive scan across the NBLK block-chunks.
// One block per class; 256 threads = 256 chunk values. In-place.
// Also emits the per-class total into g_count (atomic-free).
// ---------------------------------------------------------------------------
__global__ void k_scanA() {
    int c = blockIdx.x;
    int t = threadIdx.x;
    int v = g_hist[t * NUM_CLASSES + c];

    int lane = t & 31, w = t >> 5;
    int x = v;
    #pragma unroll
    for (int o = 1; o < 32; o <<= 1) {
        int y = __shfl_up_sync(0xffffffffu, x, o);
        if (lane >= o) x += y;
    }
    __shared__ int wt[8];
    if (lane == 31) wt[w] = x;
    __syncthreads();
    if (t == 0) {
        int s = 0;
        #pragma unroll
        for (int i = 0; i < 8; i++) { int tmp = wt[i]; wt[i] = s; s += tmp; }
    }
    __syncthreads();
    int incl = x + wt[w];
    g_hist[t * NUM_CLASSES + c] = incl - v;   // exclusive prefix within class
    if (t == NBLK - 1) g_count[c] = incl;     // class total
}

// ---------------------------------------------------------------------------
// Kernel 3: exclusive scan over 1000 class totals (single block)
// ---------------------------------------------------------------------------
__global__ void k_scanB() {
    __shared__ int s[1024];
    int t = threadIdx.x;
    s[t] = (t < NUM_CLASSES) ? g_count[t] : 0;
    for (int off = 1; off < 1024; off <<= 1) {
        __syncthreads();
        int v = (t >= off) ? s[t - off] : 0;
        __syncthreads();
        s[t] += v;
    }
    __syncthreads();
    if (t < NUM_CLASSES) g_offset[t] = (t == 0) ? 0 : s[t - 1];
}

// ---------------------------------------------------------------------------
// Kernel 4: scatter row indices, smem cursors only (no global atomics).
// Block b's class-c rows land in [g_offset[c]+pre[b][c], ... ) — disjoint.
// ---------------------------------------------------------------------------
__global__ void k_scatter(const int* __restrict__ labels, int n, int rpb) {
    __shared__ int cursor[NUM_CLASSES];
    int b = blockIdx.x;
    const int* pre = &g_hist[b * NUM_CLASSES];
    for (int c = threadIdx.x; c < NUM_CLASSES; c += blockDim.x)
        cursor[c] = g_offset[c] + pre[c];
    __syncthreads();
    int base = b * rpb;
    for (int j = threadIdx.x; j < rpb; j += blockDim.x) {
        int r = base + j;
        if (r < n) {
            int c = labels[r];
            int pos = atomicAdd(&cursor[c], 1);
            g_idx[pos] = r;
        }
    }
}

// ---------------------------------------------------------------------------
// Kernel 5: per-class coalesced segment sum + EMA epilogue.
// One block per class, one thread per feature dim. All feature reads are
// 128B-line coalesced; zero atomics. 4 accumulators for MLP.
// ---------------------------------------------------------------------------
__global__ void __launch_bounds__(256, 8)
k_reduce(const float* __restrict__ feats,
         const float* __restrict__ protos,
         float* __restrict__ out) {
    int c = blockIdx.x;
    int t = threadIdx.x;
    int start = g_offset[c];
    int cnt   = g_count[c];

    __shared__ int sidx[256];
    float s0 = 0.f, s1 = 0.f, s2 = 0.f, s3 = 0.f;

    for (int base = 0; base < cnt; base += 256) {
        int m = min(256, cnt - base);
        if (t < m) sidx[t] = g_idx[start + base + t];
        __syncthreads();
        int j = 0;
        for (; j + 4 <= m; j += 4) {
            long r0 = sidx[j + 0];
            long r1 = sidx[j + 1];
            long r2 = sidx[j + 2];
            long r3 = sidx[j + 3];
            s0 += feats[r0 * FEAT_DIM + t];
            s1 += feats[r1 * FEAT_DIM + t];
            s2 += feats[r2 * FEAT_DIM + t];
            s3 += feats[r3 * FEAT_DIM + t];
        }
        for (; j < m; j++) {
            s0 += feats[(long)sidx[j] * FEAT_DIM + t];
        }
        __syncthreads();
    }

    float sum = (s0 + s1) + (s2 + s3);
    float p = protos[c * FEAT_DIM + t];
    float r = p;
    if (cnt > 0) {
        float mean = sum / (float)cnt;
        r = 0.9f * p + 0.1f * mean;
    }
    out[c * FEAT_DIM + t] = r;
}

// ---------------------------------------------------------------------------
// Launch
// ---------------------------------------------------------------------------
extern "C" void kernel_launch(void* const* d_in, const int* in_sizes, int n_in,
                              void* d_out, int out_size) {
    const float* features   = (const float*)d_in[0];
    const int*   labels     = (const int*)d_in[1];
    const float* prototypes = (const float*)d_in[2];
    float*       out        = (float*)d_out;

    int n   = in_sizes[1];
    int rpb = (n + NBLK - 1) / NBLK;   // rows per block-chunk

    k_hist   <<<NBLK, 256>>>(labels, n, rpb);
    k_scanA  <<<NUM_CLASSES, NBLK>>>();
    k_scanB  <<<1, 1024>>>();
    k_scatter<<<NBLK, 256>>>(labels, n, rpb);
    k_reduce <<<NUM_CLASSES, 256>>>(features, prototypes, out);
}

// round 3
// speedup vs baseline: 1.3152x; 1.0847x over previous
#include <cuda_runtime.h>

#define NUM_CLASSES 1000
#define FEAT_DIM    256
#define NROWS       262144
#define NBLK        256          // chunks for hierarchical counting sort

// Device-global scratch (no allocation allowed in kernel_launch).
__device__ int g_hist[NBLK * NUM_CLASSES];   // per-block hist -> per-block excl prefix
__device__ int g_count[NUM_CLASSES];
__device__ int g_offset[NUM_CLASSES];
__device__ int g_idx[NROWS];

// ---------------------------------------------------------------------------
// Kernel 1: per-block label histogram (smem privatized, int4 label loads)
// Block b owns rows [b*rpb, (b+1)*rpb); rpb is a multiple of 4.
// ---------------------------------------------------------------------------
__global__ void k_hist(const int* __restrict__ labels, int n, int rpb) {
    __shared__ int h[NUM_CLASSES];
    for (int i = threadIdx.x; i < NUM_CLASSES; i += blockDim.x) h[i] = 0;
    __syncthreads();
    int base = blockIdx.x * rpb;
    int q    = rpb >> 2;
    const int4* lab4 = (const int4*)(labels + base);   // base % 4 == 0
    for (int j4 = threadIdx.x; j4 < q; j4 += blockDim.x) {
        int r = base + (j4 << 2);
        if (r + 3 < n) {
            int4 L = lab4[j4];
            atomicAdd(&h[L.x], 1);
            atomicAdd(&h[L.y], 1);
            atomicAdd(&h[L.z], 1);
            atomicAdd(&h[L.w], 1);
        } else {
            for (int k = 0; k < 4; k++)
                if (r + k < n) atomicAdd(&h[labels[r + k]], 1);
        }
    }
    __syncthreads();
    int* dst = &g_hist[blockIdx.x * NUM_CLASSES];
    for (int i = threadIdx.x; i < NUM_CLASSES; i += blockDim.x) dst[i] = h[i];
}

// ---------------------------------------------------------------------------
// Kernel 2: per-class exclusive scan across the NBLK block-chunks.
// One block per class; NBLK threads. In-place; emits class totals.
// ---------------------------------------------------------------------------
__global__ void k_scanA() {
    int c = blockIdx.x;
    int t = threadIdx.x;
    int v = g_hist[t * NUM_CLASSES + c];

    int lane = t & 31, w = t >> 5;
    int x = v;
    #pragma unroll
    for (int o = 1; o < 32; o <<= 1) {
        int y = __shfl_up_sync(0xffffffffu, x, o);
        if (lane >= o) x += y;
    }
    __shared__ int wt[NBLK / 32];
    if (lane == 31) wt[w] = x;
    __syncthreads();
    if (t == 0) {
        int s = 0;
        #pragma unroll
        for (int i = 0; i < NBLK / 32; i++) { int tmp = wt[i]; wt[i] = s; s += tmp; }
    }
    __syncthreads();
    int incl = x + wt[w];
    g_hist[t * NUM_CLASSES + c] = incl - v;   // exclusive prefix within class
    if (t == NBLK - 1) g_count[c] = incl;     // class total
}

// ---------------------------------------------------------------------------
// Kernel 3: exclusive scan over 1000 class totals (single block)
// ---------------------------------------------------------------------------
__global__ void k_scanB() {
    __shared__ int s[1024];
    int t = threadIdx.x;
    s[t] = (t < NUM_CLASSES) ? g_count[t] : 0;
    for (int off = 1; off < 1024; off <<= 1) {
        __syncthreads();
        int v = (t >= off) ? s[t - off] : 0;
        __syncthreads();
        s[t] += v;
    }
    __syncthreads();
    if (t < NUM_CLASSES) g_offset[t] = (t == 0) ? 0 : s[t - 1];
}

// ---------------------------------------------------------------------------
// Kernel 4: scatter row indices; smem cursors only, int4 label loads.
// ---------------------------------------------------------------------------
__global__ void k_scatter(const int* __restrict__ labels, int n, int rpb) {
    __shared__ int cursor[NUM_CLASSES];
    int b = blockIdx.x;
    const int* pre = &g_hist[b * NUM_CLASSES];
    for (int c = threadIdx.x; c < NUM_CLASSES; c += blockDim.x)
        cursor[c] = g_offset[c] + pre[c];
    __syncthreads();
    int base = b * rpb;
    int q    = rpb >> 2;
    const int4* lab4 = (const int4*)(labels + base);
    for (int j4 = threadIdx.x; j4 < q; j4 += blockDim.x) {
        int r = base + (j4 << 2);
        if (r + 3 < n) {
            int4 L = lab4[j4];
            g_idx[atomicAdd(&cursor[L.x], 1)] = r;
            g_idx[atomicAdd(&cursor[L.y], 1)] = r + 1;
            g_idx[atomicAdd(&cursor[L.z], 1)] = r + 2;
            g_idx[atomicAdd(&cursor[L.w], 1)] = r + 3;
        } else {
            for (int k = 0; k < 4; k++)
                if (r + k < n) {
                    int c = labels[r + k];
                    g_idx[atomicAdd(&cursor[c], 1)] = r + k;
                }
        }
    }
}

// ---------------------------------------------------------------------------
// Kernel 5: per-class segment sum with float4 loads + EMA epilogue.
// 256 threads = 4 row-groups x 64 threads. Each group covers a full 256-float
// row with 64 LDG.128s; groups take rows j ≡ grp (mod 4). Cross-group combine
// in smem at the end. One read per feature element, zero atomics.
// ---------------------------------------------------------------------------
__global__ void __launch_bounds__(256, 8)
k_reduce(const float4* __restrict__ feats4,
         const float* __restrict__ protos,
         float* __restrict__ out) {
    int c   = blockIdx.x;
    int t   = threadIdx.x;
    int grp = t >> 6;     // 0..3: row group
    int col = t & 63;     // float4 column within the row
    int start = g_offset[c];
    int cnt   = g_count[c];

    __shared__ int sidx[256];
    float4 a0 = make_float4(0.f, 0.f, 0.f, 0.f);
    float4 a1 = make_float4(0.f, 0.f, 0.f, 0.f);

    for (int base = 0; base < cnt; base += 256) {
        int m = min(256, cnt - base);
        if (t < m) sidx[t] = g_idx[start + base + t];
        __syncthreads();
        int j = grp;
        for (; j + 4 < m; j += 8) {
            long r0 = sidx[j];
            long r1 = sidx[j + 4];
            float4 v0 = feats4[r0 * (FEAT_DIM / 4) + col];
            float4 v1 = feats4[r1 * (FEAT_DIM / 4) + col];
            a0.x += v0.x; a0.y += v0.y; a0.z += v0.z; a0.w += v0.w;
            a1.x += v1.x; a1.y += v1.y; a1.z += v1.z; a1.w += v1.w;
        }
        for (; j < m; j += 4) {
            float4 v = feats4[(long)sidx[j] * (FEAT_DIM / 4) + col];
            a0.x += v.x; a0.y += v.y; a0.z += v.z; a0.w += v.w;
        }
        __syncthreads();
    }

    // Combine the 4 per-group partials.
    __shared__ float4 part4[4][64];   // 4 KB
    float4 a = make_float4(a0.x + a1.x, a0.y + a1.y, a0.z + a1.z, a0.w + a1.w);
    part4[grp][col] = a;
    __syncthreads();

    const float* part = (const float*)part4;   // part[g*256 + column]
    float sum = part[0 * 256 + t] + part[1 * 256 + t]
              + part[2 * 256 + t] + part[3 * 256 + t];

    float p = protos[c * FEAT_DIM + t];
    float r = p;
    if (cnt > 0) {
        float mean = sum / (float)cnt;
        r = 0.9f * p + 0.1f * mean;
    }
    out[c * FEAT_DIM + t] = r;
}

// ---------------------------------------------------------------------------
// Launch
// ---------------------------------------------------------------------------
extern "C" void kernel_launch(void* const* d_in, const int* in_sizes, int n_in,
                              void* d_out, int out_size) {
    const float* features   = (const float*)d_in[0];
    const int*   labels     = (const int*)d_in[1];
    const float* prototypes = (const float*)d_in[2];
    float*       out        = (float*)d_out;

    int n = in_sizes[1];
    // rows per block-chunk, multiple of 4 so int4 loads stay aligned
    int rpb = ((n + NBLK * 4 - 1) / (NBLK * 4)) * 4;

    k_hist   <<<NBLK, 256>>>(labels, n, rpb);
    k_scanA  <<<NUM_CLASSES, NBLK>>>();
    k_scanB  <<<1, 1024>>>();
    k_scatter<<<NBLK, 256>>>(labels, n, rpb);
    k_reduce <<<NUM_CLASSES, 256>>>((const float4*)features, prototypes, out);
}